// round 2
// baseline (speedup 1.0000x reference)
#include <cuda_runtime.h>

// Problem constants (fixed by reference setup_inputs)
#define NB  8      // batch
#define CCH 512    // channels
#define NH  8      // heads
#define DD  64     // head dim
#define LL  64     // token length
#define CTK 256    // token channels
#define HW  16384  // 128*128 pixels

// Scratch (device globals — no allocations allowed)
__device__ __align__(16) float g_k [NB * CCH * LL];  // [n][h][d][l], pre-scaled by 1/8
__device__ __align__(16) float g_vt[NB * CCH * LL];  // [n][h][l][d] (transposed V)

// ---- packed f32x2 helpers (FFMA2 is PTX-only; ptxas never auto-fuses) ----
__device__ __forceinline__ unsigned long long pack2(float a, float b) {
    unsigned long long r;
    asm("mov.b64 %0, {%1, %2};" : "=l"(r) : "f"(a), "f"(b));
    return r;
}
__device__ __forceinline__ void unpack2(unsigned long long v, float& a, float& b) {
    asm("mov.b64 {%0, %1}, %2;" : "=f"(a), "=f"(b) : "l"(v));
}
__device__ __forceinline__ void ffma2(unsigned long long& d,
                                      unsigned long long a, unsigned long long b) {
    asm("fma.rn.f32x2 %0, %1, %2, %0;" : "+l"(d) : "l"(a), "l"(b));
}

// ============================================================================
// Kernel 1: fused V/K projections (1x1 conv == pointwise GEMM, K=256)
//   v[n,o,l] = sum_ct Wv[o,ct]*token[n,ct,l] + bv[o]
//   k scaled by 1/8 here so the attention kernel needs no scale.
//   K stored d-major, V stored l-major (transposed) for packed smem reads.
// Grid: 8*512 blocks, 64 threads (thread = l)
// ============================================================================
__global__ void vk_kernel(const float* __restrict__ token,
                          const float* __restrict__ Wv, const float* __restrict__ bv,
                          const float* __restrict__ Wk, const float* __restrict__ bk) {
    __shared__ float wv_s[CTK];
    __shared__ float wk_s[CTK];
    const int o = blockIdx.x & (CCH - 1);
    const int n = blockIdx.x >> 9;
    const int l = threadIdx.x;

#pragma unroll
    for (int i = 0; i < 4; i++) {
        wv_s[l + 64 * i] = Wv[o * CTK + l + 64 * i];
        wk_s[l + 64 * i] = Wk[o * CTK + l + 64 * i];
    }
    __syncthreads();

    const float* tok = token + n * (CTK * LL) + l;
    float av0 = 0.f, av1 = 0.f, ak0 = 0.f, ak1 = 0.f;
#pragma unroll 8
    for (int ct = 0; ct < CTK; ct += 2) {
        float t0 = tok[ct * LL];
        float t1 = tok[(ct + 1) * LL];
        av0 = fmaf(wv_s[ct],     t0, av0);
        ak0 = fmaf(wk_s[ct],     t0, ak0);
        av1 = fmaf(wv_s[ct + 1], t1, av1);
        ak1 = fmaf(wk_s[ct + 1], t1, ak1);
    }
    float av = av0 + av1 + bv[o];
    float ak = (ak0 + ak1 + bk[o]) * 0.125f;  // 1/sqrt(C/h) = 1/8

    const int h = o >> 6, d = o & 63;
    const int slice = (n * NH + h) * (DD * LL);
    g_k [slice + d * LL + l] = ak;   // coalesced over l
    g_vt[slice + l * DD + d] = av;   // transposed scatter (tiny, one-time)
}

// ============================================================================
// Kernel 2: per-pixel attention, f32x2 packed FMA throughout.
// Block = 256 pixels of one (n,h). K,V tiles (32 KB) live in smem; every
// GEMV inner product runs as 32 independent packed accumulators fed by
// broadcast LDS.128 (all lanes same address -> conflict-free).
// Grid: 8*8*64 = 4096 blocks.
// ============================================================================
__global__ __launch_bounds__(256, 1)
void attn_kernel(const float* __restrict__ feature, float* __restrict__ out) {
    __shared__ __align__(16) float k_s[DD * LL];
    __shared__ __align__(16) float v_s[LL * DD];

    const int tid  = threadIdx.x;
    const int tile = blockIdx.x & 63;
    const int nh   = blockIdx.x >> 6;

    // Stage K (d-major) and V^T (l-major) tiles into smem, float4 copies.
    {
        const float4* gk4 = reinterpret_cast<const float4*>(g_k)  + nh * 1024;
        const float4* gv4 = reinterpret_cast<const float4*>(g_vt) + nh * 1024;
        float4* ks4 = reinterpret_cast<float4*>(k_s);
        float4* vs4 = reinterpret_cast<float4*>(v_s);
#pragma unroll
        for (int i = 0; i < 4; i++) {
            ks4[tid + 256 * i] = gk4[tid + 256 * i];
            vs4[tid + 256 * i] = gv4[tid + 256 * i];
        }
    }
    __syncthreads();

    const int base = nh * (DD * HW) + tile * 256 + tid;
    const float* f = feature + base;

    // ---- load q (64 values, strided by HW; coalesced across the warp) ----
    float q[DD];
#pragma unroll
    for (int d = 0; d < DD; d++) q[d] = f[d * HW];

    // ---- GEMV 1: logits[l] = sum_d q[d] * k_s[d][l]  (k pre-scaled) ----
    unsigned long long acc[32];
#pragma unroll
    for (int j = 0; j < 32; j++) acc[j] = 0ull;
#pragma unroll
    for (int d = 0; d < DD; d++) {
        unsigned long long qq = pack2(q[d], q[d]);
        const ulonglong2* kr = reinterpret_cast<const ulonglong2*>(k_s + d * LL);
#pragma unroll
        for (int j = 0; j < 16; j++) {
            ulonglong2 kk = kr[j];          // LDS.128 broadcast
            ffma2(acc[2 * j],     qq, kk.x);
            ffma2(acc[2 * j + 1], qq, kk.y);
        }
    }

    // ---- softmax over L=64 (registers only) ----
    float lg[LL];
#pragma unroll
    for (int j = 0; j < 32; j++) unpack2(acc[j], lg[2 * j], lg[2 * j + 1]);

    float t[32];
#pragma unroll
    for (int j = 0; j < 32; j++) t[j] = fmaxf(lg[2 * j], lg[2 * j + 1]);
#pragma unroll
    for (int s = 16; s > 0; s >>= 1) {
#pragma unroll
        for (int i = 0; i < 16; i++) if (i < s) t[i] = fmaxf(t[i], t[i + s]);
    }
    const float m = t[0];
#pragma unroll
    for (int i = 0; i < LL; i++) lg[i] = __expf(lg[i] - m);
#pragma unroll
    for (int j = 0; j < 32; j++) t[j] = lg[2 * j] + lg[2 * j + 1];
#pragma unroll
    for (int s = 16; s > 0; s >>= 1) {
#pragma unroll
        for (int i = 0; i < 16; i++) if (i < s) t[i] = t[i] + t[i + s];
    }
    const float inv = __frcp_rn(t[0]);

    // ---- GEMV 2: proj[d] = sum_l v[d][l] * coef[l], packed over d-pairs ----
    unsigned long long pr[32];
#pragma unroll
    for (int j = 0; j < 32; j++) pr[j] = 0ull;
#pragma unroll
    for (int l = 0; l < LL; l++) {
        float c = lg[l] * inv;
        unsigned long long cc = pack2(c, c);
        const ulonglong2* vr = reinterpret_cast<const ulonglong2*>(v_s + l * DD);
#pragma unroll
        for (int j = 0; j < 16; j++) {
            ulonglong2 vv = vr[j];          // LDS.128 broadcast
            ffma2(pr[2 * j],     vv.x, cc);
            ffma2(pr[2 * j + 1], vv.y, cc);
        }
    }

    // ---- epilogue: residual add + store (feature re-read is L2-hot) ----
    float* o = out + base;
#pragma unroll
    for (int j = 0; j < 32; j++) {
        float p0, p1;
        unpack2(pr[j], p0, p1);
        o[(2 * j) * HW]     = f[(2 * j) * HW]     + p0;
        o[(2 * j + 1) * HW] = f[(2 * j + 1) * HW] + p1;
    }
}

// ============================================================================
extern "C" void kernel_launch(void* const* d_in, const int* in_sizes, int n_in,
                              void* d_out, int out_size) {
    const float* feature = (const float*)d_in[0];
    const float* token   = (const float*)d_in[1];
    const float* Wv      = (const float*)d_in[2];
    const float* bv      = (const float*)d_in[3];
    const float* Wk      = (const float*)d_in[4];
    const float* bk      = (const float*)d_in[5];
    float* out = (float*)d_out;

    vk_kernel<<<NB * CCH, 64>>>(token, Wv, bv, Wk, bk);
    attn_kernel<<<NB * NH * 64, 256>>>(feature, out);
}

// round 3
// speedup vs baseline: 1.2828x; 1.2828x over previous
#include <cuda_runtime.h>

// Problem constants (fixed by reference setup_inputs)
#define NB  8      // batch
#define CCH 512    // channels
#define NH  8      // heads
#define DD  64     // head dim
#define LL  64     // token length
#define CTK 256    // token channels
#define HW  16384  // 128*128 pixels

// Scratch (device globals — no allocations allowed)
__device__ __align__(16) float g_k [NB * CCH * LL];  // [nh][d][l], pre-scaled by 1/8
__device__ __align__(16) float g_vt[NB * CCH * LL];  // [nh][l][d] (transposed V)

// ---- packed f32x2 helpers (FFMA2 is PTX-only; ptxas never auto-fuses) ----
__device__ __forceinline__ unsigned long long pack2(float a, float b) {
    unsigned long long r;
    asm("mov.b64 %0, {%1, %2};" : "=l"(r) : "f"(a), "f"(b));
    return r;
}
__device__ __forceinline__ void unpack2(unsigned long long v, float& a, float& b) {
    asm("mov.b64 {%0, %1}, %2;" : "=f"(a), "=f"(b) : "l"(v));
}
__device__ __forceinline__ void ffma2(unsigned long long& d,
                                      unsigned long long a, unsigned long long b) {
    asm("fma.rn.f32x2 %0, %1, %2, %0;" : "+l"(d) : "l"(a), "l"(b));
}

// ============================================================================
// Kernel 1: fused V/K projections (1x1 conv == pointwise GEMM, K=256)
// K stored d-major (pre-scaled by 1/8), V stored l-major (transposed).
// ============================================================================
__global__ void vk_kernel(const float* __restrict__ token,
                          const float* __restrict__ Wv, const float* __restrict__ bv,
                          const float* __restrict__ Wk, const float* __restrict__ bk) {
    __shared__ float wv_s[CTK];
    __shared__ float wk_s[CTK];
    const int o = blockIdx.x & (CCH - 1);
    const int n = blockIdx.x >> 9;
    const int l = threadIdx.x;

#pragma unroll
    for (int i = 0; i < 4; i++) {
        wv_s[l + 64 * i] = Wv[o * CTK + l + 64 * i];
        wk_s[l + 64 * i] = Wk[o * CTK + l + 64 * i];
    }
    __syncthreads();

    const float* tok = token + n * (CTK * LL) + l;
    float av0 = 0.f, av1 = 0.f, ak0 = 0.f, ak1 = 0.f;
#pragma unroll 8
    for (int ct = 0; ct < CTK; ct += 2) {
        float t0 = tok[ct * LL];
        float t1 = tok[(ct + 1) * LL];
        av0 = fmaf(wv_s[ct],     t0, av0);
        ak0 = fmaf(wk_s[ct],     t0, ak0);
        av1 = fmaf(wv_s[ct + 1], t1, av1);
        ak1 = fmaf(wk_s[ct + 1], t1, ak1);
    }
    float av = av0 + av1 + bv[o];
    float ak = (ak0 + ak1 + bk[o]) * 0.125f;  // 1/sqrt(C/h) = 1/8

    const int h = o >> 6, d = o & 63;
    const int slice = (n * NH + h) * (DD * LL);
    g_k [slice + d * LL + l] = ak;
    g_vt[slice + l * DD + d] = av;
}

// ============================================================================
// Kernel 2: register-blocked attention GEMMs.
// Block = 256 threads (8 warps) = 256 pixels of one (n,h).
// Warp GEMM 32x64x64: thread tile = 8 pixels x 8 outputs (lane = pi*8 + li).
// K/V rows chunk-swizzled for conflict-free stride-32B fragment reads.
// Smem (dynamic 96KB): k_s 16K | v_s 16K | ws 8x8K (per-warp Q then Coef^T).
// ============================================================================
__global__ __launch_bounds__(256, 2)
void attn_kernel(const float* __restrict__ feature, float* __restrict__ out) {
    extern __shared__ __align__(16) float smem[];
    float* k_s = smem;              // [64 d][64 l] swizzled, 4096 floats
    float* v_s = smem + 4096;       // [64 l][64 d] swizzled, 4096 floats
    float* ws  = smem + 8192;       // 8 warps x 2048 floats (Q then Coef^T)

    const int tid  = threadIdx.x;
    const int warp = tid >> 5;
    const int lane = tid & 31;
    const int pi   = lane >> 3;     // pixel group 0..3
    const int li   = lane & 7;      // output group 0..7
    const int tile = blockIdx.x & 63;
    const int nh   = blockIdx.x >> 6;

    // ---- stage K and V tiles with 16B-chunk swizzle c' = (c>>1)|((c&1)<<3) ----
    {
        const float4* gk4 = reinterpret_cast<const float4*>(g_k)  + nh * 1024;
        const float4* gv4 = reinterpret_cast<const float4*>(g_vt) + nh * 1024;
        float4* ks4 = reinterpret_cast<float4*>(k_s);
        float4* vs4 = reinterpret_cast<float4*>(v_s);
#pragma unroll
        for (int i = 0; i < 4; i++) {
            int idx = tid + 256 * i;                 // float4 index, 0..1023
            int row = idx >> 4, c = idx & 15;
            int cs  = (c >> 1) | ((c & 1) << 3);
            ks4[row * 16 + cs] = gk4[idx];
            vs4[row * 16 + cs] = gv4[idx];
        }
    }

    const int pixbase = tile * 256 + warp * 32;
    const float* f = feature + nh * (DD * HW) + pixbase;
    float* wsw = ws + warp * 2048;

    // ---- stage Q tile: [64 d][32 p] per warp, coalesced ----
    {
        const int dq = lane >> 3;           // 0..3
        const int xq = (lane & 7) * 4;      // 0,4,...,28
#pragma unroll
        for (int s = 0; s < 16; s++) {
            int d = s * 4 + dq;
            *reinterpret_cast<float4*>(wsw + d * 32 + xq) =
                *reinterpret_cast<const float4*>(f + d * HW + xq);
        }
    }
    __syncthreads();

    // ---- GEMM1: logits[32p][64l] = Q[32p][64d] * K[64d][64l] ----
    unsigned long long acc[8][4];
#pragma unroll
    for (int j = 0; j < 8; j++)
#pragma unroll
        for (int ii = 0; ii < 4; ii++) acc[j][ii] = 0ull;

#pragma unroll 4
    for (int d = 0; d < DD; d++) {
        float4 qf0 = *reinterpret_cast<const float4*>(wsw + d * 32 + pi * 8);
        float4 qf1 = *reinterpret_cast<const float4*>(wsw + d * 32 + pi * 8 + 4);
        ulonglong2 ka = *reinterpret_cast<const ulonglong2*>(k_s + d * 64 + li * 4);
        ulonglong2 kb = *reinterpret_cast<const ulonglong2*>(k_s + d * 64 + 32 + li * 4);
        unsigned long long qq[8];
        qq[0] = pack2(qf0.x, qf0.x); qq[1] = pack2(qf0.y, qf0.y);
        qq[2] = pack2(qf0.z, qf0.z); qq[3] = pack2(qf0.w, qf0.w);
        qq[4] = pack2(qf1.x, qf1.x); qq[5] = pack2(qf1.y, qf1.y);
        qq[6] = pack2(qf1.z, qf1.z); qq[7] = pack2(qf1.w, qf1.w);
#pragma unroll
        for (int j = 0; j < 8; j++) {
            ffma2(acc[j][0], qq[j], ka.x);
            ffma2(acc[j][1], qq[j], ka.y);
            ffma2(acc[j][2], qq[j], kb.x);
            ffma2(acc[j][3], qq[j], kb.y);
        }
    }

    // ---- softmax per pixel row (8 rows x 8 local l; reduce over 8 li-lanes) ----
    float lg[8][8];
#pragma unroll
    for (int j = 0; j < 8; j++)
#pragma unroll
        for (int ii = 0; ii < 4; ii++) unpack2(acc[j][ii], lg[j][2 * ii], lg[j][2 * ii + 1]);

    float inv[8];
#pragma unroll
    for (int j = 0; j < 8; j++) {
        float m = lg[j][0];
#pragma unroll
        for (int i = 1; i < 8; i++) m = fmaxf(m, lg[j][i]);
        m = fmaxf(m, __shfl_xor_sync(0xffffffffu, m, 1));
        m = fmaxf(m, __shfl_xor_sync(0xffffffffu, m, 2));
        m = fmaxf(m, __shfl_xor_sync(0xffffffffu, m, 4));
        float s = 0.f;
#pragma unroll
        for (int i = 0; i < 8; i++) { lg[j][i] = __expf(lg[j][i] - m); s += lg[j][i]; }
        s += __shfl_xor_sync(0xffffffffu, s, 1);
        s += __shfl_xor_sync(0xffffffffu, s, 2);
        s += __shfl_xor_sync(0xffffffffu, s, 4);
        inv[j] = __frcp_rn(s);
    }

    // ---- write Coef^T [64 l][32 p] into ws (overwrites Q) ----
    __syncwarp();
#pragma unroll
    for (int i = 0; i < 8; i++) {
        float4 a, b;
        a.x = lg[0][i] * inv[0]; a.y = lg[1][i] * inv[1];
        a.z = lg[2][i] * inv[2]; a.w = lg[3][i] * inv[3];
        b.x = lg[4][i] * inv[4]; b.y = lg[5][i] * inv[5];
        b.z = lg[6][i] * inv[6]; b.w = lg[7][i] * inv[7];
        *reinterpret_cast<float4*>(wsw + (li * 8 + i) * 32 + pi * 8)     = a;
        *reinterpret_cast<float4*>(wsw + (li * 8 + i) * 32 + pi * 8 + 4) = b;
    }
    __syncwarp();

    // ---- GEMM2: out[32p][64d] = Coef[32p][64l] * V[64l][64d] ----
    unsigned long long pr[8][4];
#pragma unroll
    for (int j = 0; j < 8; j++)
#pragma unroll
        for (int ii = 0; ii < 4; ii++) pr[j][ii] = 0ull;

#pragma unroll 4
    for (int l = 0; l < LL; l++) {
        float4 cf0 = *reinterpret_cast<const float4*>(wsw + l * 32 + pi * 8);
        float4 cf1 = *reinterpret_cast<const float4*>(wsw + l * 32 + pi * 8 + 4);
        ulonglong2 va = *reinterpret_cast<const ulonglong2*>(v_s + l * 64 + li * 4);
        ulonglong2 vb = *reinterpret_cast<const ulonglong2*>(v_s + l * 64 + 32 + li * 4);
        unsigned long long cc[8];
        cc[0] = pack2(cf0.x, cf0.x); cc[1] = pack2(cf0.y, cf0.y);
        cc[2] = pack2(cf0.z, cf0.z); cc[3] = pack2(cf0.w, cf0.w);
        cc[4] = pack2(cf1.x, cf1.x); cc[5] = pack2(cf1.y, cf1.y);
        cc[6] = pack2(cf1.z, cf1.z); cc[7] = pack2(cf1.w, cf1.w);
#pragma unroll
        for (int j = 0; j < 8; j++) {
            ffma2(pr[j][0], cc[j], va.x);
            ffma2(pr[j][1], cc[j], va.y);
            ffma2(pr[j][2], cc[j], vb.x);
            ffma2(pr[j][3], cc[j], vb.y);
        }
    }

    // ---- epilogue: residual add (feature re-read, L2-hot) + store ----
    float* o = out + nh * (DD * HW) + pixbase;
#pragma unroll
    for (int ii = 0; ii < 4; ii++) {
        int d0 = li * 8 + 2 * ii;
        float p0[8], p1[8];
#pragma unroll
        for (int j = 0; j < 8; j++) unpack2(pr[j][ii], p0[j], p1[j]);

        float4 fa0 = *reinterpret_cast<const float4*>(f + d0 * HW + pi * 8);
        float4 fa1 = *reinterpret_cast<const float4*>(f + d0 * HW + pi * 8 + 4);
        float4 fb0 = *reinterpret_cast<const float4*>(f + (d0 + 1) * HW + pi * 8);
        float4 fb1 = *reinterpret_cast<const float4*>(f + (d0 + 1) * HW + pi * 8 + 4);

        float4 oa0, oa1, ob0, ob1;
        oa0.x = fa0.x + p0[0]; oa0.y = fa0.y + p0[1]; oa0.z = fa0.z + p0[2]; oa0.w = fa0.w + p0[3];
        oa1.x = fa1.x + p0[4]; oa1.y = fa1.y + p0[5]; oa1.z = fa1.z + p0[6]; oa1.w = fa1.w + p0[7];
        ob0.x = fb0.x + p1[0]; ob0.y = fb0.y + p1[1]; ob0.z = fb0.z + p1[2]; ob0.w = fb0.w + p1[3];
        ob1.x = fb1.x + p1[4]; ob1.y = fb1.y + p1[5]; ob1.z = fb1.z + p1[6]; ob1.w = fb1.w + p1[7];

        *reinterpret_cast<float4*>(o + d0 * HW + pi * 8)           = oa0;
        *reinterpret_cast<float4*>(o + d0 * HW + pi * 8 + 4)       = oa1;
        *reinterpret_cast<float4*>(o + (d0 + 1) * HW + pi * 8)     = ob0;
        *reinterpret_cast<float4*>(o + (d0 + 1) * HW + pi * 8 + 4) = ob1;
    }
}

// ============================================================================
extern "C" void kernel_launch(void* const* d_in, const int* in_sizes, int n_in,
                              void* d_out, int out_size) {
    const float* feature = (const float*)d_in[0];
    const float* token   = (const float*)d_in[1];
    const float* Wv      = (const float*)d_in[2];
    const float* bv      = (const float*)d_in[3];
    const float* Wk      = (const float*)d_in[4];
    const float* bk      = (const float*)d_in[5];
    float* out = (float*)d_out;

    const int smem_bytes = 96 * 1024;
    cudaFuncSetAttribute(attn_kernel, cudaFuncAttributeMaxDynamicSharedMemorySize, smem_bytes);

    vk_kernel<<<NB * CCH, 64>>>(token, Wv, bv, Wk, bk);
    attn_kernel<<<NB * NH * 64, 256, smem_bytes>>>(feature, out);
}